// round 5
// baseline (speedup 1.0000x reference)
#include <cuda_runtime.h>
#include <cuda_fp16.h>
#include <math.h>
#include <stdint.h>

// ---------------- problem constants ----------------
#define KST   16
#define CDIM  64
#define TDIM  65536
#define KTOT  576            // 64*9 contraction length
#define TM    128            // time rows per tile (GEMM M)
#define ASTR  1168           // smem row stride bytes (584 halves)
#define SGRP  8              // states per block (2-way split)

// ---------------- device scratch ----------------
__device__ float  g_Linv[KST * CDIM * CDIM];
__device__ float  g_logdet[KST];
__device__ float  g_beff[KST * CDIM];
__device__ __half g_WeffH[KST * CDIM * KTOT];   // [k][c][e], e = ci*9+j

// ---------------- helpers ----------------
__device__ __forceinline__ uint32_t s2u(const void* p) {
    uint32_t a;
    asm("{ .reg .u64 t; cvta.to.shared.u64 t, %1; cvt.u32.u64 %0, t; }" : "=r"(a) : "l"(p));
    return a;
}
__device__ __forceinline__ void ldsm4(uint32_t* r, uint32_t addr) {
    asm volatile("ldmatrix.sync.aligned.m8n8.x4.shared.b16 {%0,%1,%2,%3}, [%4];"
                 : "=r"(r[0]), "=r"(r[1]), "=r"(r[2]), "=r"(r[3]) : "r"(addr));
}
__device__ __forceinline__ void mma16816(float* d, const uint32_t* a, const uint32_t* b) {
    asm volatile(
        "mma.sync.aligned.m16n8k16.row.col.f32.f16.f16.f32 "
        "{%0,%1,%2,%3}, {%4,%5,%6,%7}, {%8,%9}, {%0,%1,%2,%3};"
        : "+f"(d[0]), "+f"(d[1]), "+f"(d[2]), "+f"(d[3])
        : "r"(a[0]), "r"(a[1]), "r"(a[2]), "r"(a[3]), "r"(b[0]), "r"(b[1]));
}
__device__ __forceinline__ void cpasync16(uint32_t dst, const void* src) {
    asm volatile("cp.async.cg.shared.global [%0], [%1], 16;" :: "r"(dst), "l"(src));
}
#define CP_COMMIT() asm volatile("cp.async.commit_group;" ::: "memory")
#define CP_WAIT1()  asm volatile("cp.async.wait_group 1;" ::: "memory")

// ================= 1) warp-per-state Cholesky + L^{-1} (no block barriers) =================
// grid 16 x 32 threads. Deferred-normalization elimination, column-parallel
// forward substitution, warp-shuffle logdet.
__global__ void chol_kernel(const float* __restrict__ Sigma, const float* __restrict__ b) {
    const int k = blockIdx.x;
    const int lane = threadIdx.x;   // 32
    __shared__ float S[CDIM * 65];
    __shared__ float Yt[CDIM * 65];   // Yt[c*65+i] = Y[i][c]
    __shared__ float sinv[CDIM], sq[CDIM], lgs[CDIM];

    for (int idx = lane; idx < CDIM * CDIM; idx += 32)
        S[(idx >> 6) * 65 + (idx & 63)] = Sigma[k * CDIM * CDIM + idx];
    __syncwarp();

    // ---- deferred-normalization Cholesky (LDL-style elimination) ----
    for (int kk = 0; kk < CDIM - 1; kk++) {
        const float dinv = 1.f / S[kk * 65 + kk];
        int r = lane;
        if (r > kk) {
            const float srk = S[r * 65 + kk] * dinv;
            for (int j = kk + 1; j <= r; j++)
                S[r * 65 + j] -= srk * S[j * 65 + kk];
        }
        r = lane + 32;
        if (r > kk) {
            const float srk = S[r * 65 + kk] * dinv;
            for (int j = kk + 1; j <= r; j++)
                S[r * 65 + j] -= srk * S[j * 65 + kk];
        }
        __syncwarp();
    }

    // diag terms: d_i = S[i][i] = L_ii^2
    #pragma unroll
    for (int p = 0; p < 2; p++) {
        const int i = lane + 32 * p;
        const float d = S[i * 65 + i];
        sinv[i] = 1.f / d;
        sq[i]   = sqrtf(d);
        lgs[i]  = logf(d);
    }
    __syncwarp();

    // logdet = sum log d_i  (warp reduce)
    {
        float ld = lgs[lane] + lgs[lane + 32];
        #pragma unroll
        for (int o = 16; o; o >>= 1) ld += __shfl_xor_sync(0xffffffffu, ld, o);
        if (lane == 0) g_logdet[k] = ld;
    }

    // ---- forward substitution, 2 columns per lane (serial in-lane) ----
    // Y[i][c] = sinv[i] * (delta_ic - sum_{j<i} S[i][j] * Y[j][c]);  Linv[i][c] = Y[i][c]*sq[i]
    #pragma unroll
    for (int pass = 0; pass < 2; pass++) {
        const int c = lane + 32 * pass;
        float* Yc = &Yt[c * 65];
        Yc[c] = sinv[c];
        for (int i = c + 1; i < CDIM; i++) {
            float t = 0.f;
            const float* Si = &S[i * 65];
            for (int j = c; j < i; j++) t -= Si[j] * Yc[j];
            Yc[i] = t * sinv[i];
        }
    }
    __syncwarp();

    // beff[r] = sq[r] * sum_m Yt[m][r] * b[m]
    #pragma unroll
    for (int p = 0; p < 2; p++) {
        const int r = lane + 32 * p;
        float a = 0.f;
        for (int m = 0; m <= r; m++) a += Yt[m * 65 + r] * b[k * CDIM + m];
        g_beff[k * CDIM + r] = a * sq[r];
    }
    // Linv[i][c] = Yt[c][i] * sq[i]
    for (int idx = lane; idx < CDIM * CDIM; idx += 32) {
        const int i = idx >> 6, c = idx & 63;
        g_Linv[k * CDIM * CDIM + idx] = (c <= i) ? Yt[c * 65 + i] * sq[i] : 0.f;
    }
}

// ========== 2) Weff = Linv @ W -> fp16 packed [k][c][576] ==========
// grid (8 splits, 16 k), 256 threads. Split s covers e in [72s, 72s+72).
__global__ void weff_pack_kernel(const float* __restrict__ W) {
    const int s = blockIdx.x;
    const int k = blockIdx.y;
    const int tid = threadIdx.x;
    __shared__ float Xs[CDIM * 65];
    __shared__ float Ws[CDIM * 73];

    for (int idx = tid; idx < CDIM * CDIM; idx += 256)
        Xs[(idx >> 6) * 65 + (idx & 63)] = g_Linv[k * CDIM * CDIM + idx];
    for (int idx = tid; idx < CDIM * 72; idx += 256) {
        const int m = idx / 72, e = idx - m * 72;
        Ws[m * 73 + e] = W[k * CDIM * KTOT + m * KTOT + s * 72 + e];
    }
    __syncthreads();

    const int c = tid & 63;
    const int grp = tid >> 6;
    float Lr[CDIM];
    #pragma unroll
    for (int m = 0; m < CDIM; m++) Lr[m] = Xs[c * 65 + m];

    for (int eo = grp; eo < 72; eo += 4) {
        float acc = 0.f;
        #pragma unroll
        for (int m = 0; m < CDIM; m++) acc += Lr[m] * Ws[m * 73 + eo];
        g_WeffH[((size_t)k * CDIM + c) * KTOT + s * 72 + eo] = __float2half(acc);
    }
}

// ================= 3) main: smem im2col A + mma.sync fp16, 8 warps =================
// grid 1024: tile = bx>>1 (512 t-tiles), state group sg = bx&1 (8 states each).
// smem bytes: A [0,149504), B [149504,224256), beff, logd, red
#define SMA   0
#define SMB   149504
#define SMBE  224256
#define SMLD  228352
#define SMRED 228416
#define SMTOT 228928

__device__ __forceinline__ void loadB(uint32_t sbB, int k, int h, int tid) {
    // half h: 288 halves per row starting at byte col h*576; 64 rows x 36 chunks
    #pragma unroll
    for (int i = 0; i < 9; i++) {
        const int lin = i * 256 + tid;          // 0..2303
        const int row = lin / 36, ch = lin - row * 36;
        const uint32_t dst = sbB + row * ASTR + h * 576 + ch * 16;
        const char* src = (const char*)g_WeffH +
                          ((size_t)k * CDIM + row) * (KTOT * 2) + h * 576 + ch * 16;
        cpasync16(dst, src);
    }
}

__global__ void __launch_bounds__(256, 1)
main_kernel(const float* __restrict__ x, float* __restrict__ out) {
    extern __shared__ __align__(1024) char smem[];
    const uint32_t sb = s2u(smem);
    const int tid = threadIdx.x;
    const int lane = tid & 31;
    const int w = tid >> 5;           // 8 warps
    const int wm = w & 3;             // M: rows [wm*32, +32)
    const int wn = w >> 2;            // N: cols [wn*32, +32)
    const int t0 = (blockIdx.x >> 1) * TM;
    const int k0 = (blockIdx.x & 1) * SGRP;

    float* beff_s = (float*)(smem + SMBE);
    float* logd_s = (float*)(smem + SMLD);
    float* red    = (float*)(smem + SMRED);

    // prefetch B for half-steps 0 and 1 (state k0)
    loadB(sb + SMB, k0, 0, tid); CP_COMMIT();
    loadB(sb + SMB, k0, 1, tid); CP_COMMIT();

    // ---- build A (im2col fp16): 2 threads per row, 16 channel-pairs each ----
    {
        const int row = tid >> 1, half = tid & 1;
        __half* Arow = (__half*)(smem + SMA + row * ASTR);
        const int tb = t0 + row - 8;
        #pragma unroll 4
        for (int pp = 0; pp < 16; pp++) {
            const int p = half * 16 + pp;        // channel pair (2p, 2p+1)
            float v[18];
            const float* x0 = x + (size_t)(2 * p) * TDIM;
            const float* x1 = x0 + TDIM;
            #pragma unroll
            for (int j = 0; j < 9; j++) {
                const int gt = tb + j;
                v[j]     = (gt >= 0) ? __ldg(x0 + gt) : 0.f;
                v[9 + j] = (gt >= 0) ? __ldg(x1 + gt) : 0.f;
            }
            uint32_t* dst = (uint32_t*)(Arow + p * 18);   // 36B-aligned
            #pragma unroll
            for (int qq = 0; qq < 9; qq++) {
                __half2 hh = __floats2half2_rn(v[2 * qq], v[2 * qq + 1]);
                dst[qq] = *(uint32_t*)&hh;
            }
        }
    }
    for (int idx = tid; idx < KST * CDIM; idx += 256) beff_s[idx] = g_beff[idx];
    if (tid < KST) logd_s[tid] = g_logdet[tid];

    // ldmatrix per-thread base addresses
    const int mat = lane >> 3, lr = lane & 7;
    const uint32_t aBase = sb + SMA + (wm * 32 + (mat & 1) * 8 + lr) * ASTR + (mat >> 1) * 16;
    const uint32_t bBase = sb + SMB + (wn * 32 + (mat >> 1) * 8 + lr) * ASTR + (mat & 1) * 16;
    const int g = lane >> 2, tig = lane & 3;

    float acc[2][4][4];
    #pragma unroll
    for (int mt = 0; mt < 2; mt++)
        #pragma unroll
        for (int nt = 0; nt < 4; nt++)
            #pragma unroll
            for (int i = 0; i < 4; i++) acc[mt][nt][i] = 0.f;

    CP_WAIT1();              // half-step 0 resident
    __syncthreads();         // A + B(k0,0) visible everywhere

    const int NHALF = 2 * SGRP;
    for (int s = 0; s < NHALF; s++) {
        const int k = k0 + (s >> 1), h = s & 1;

        // ---- compute half-step s : k-steps [h*18, h*18+18) ----
        #pragma unroll 3
        for (int kk = h * 18; kk < h * 18 + 18; kk++) {
            uint32_t a[2][4], b[2][4];
            ldsm4(a[0], aBase + kk * 32);
            ldsm4(a[1], aBase + 16 * ASTR + kk * 32);
            ldsm4(b[0], bBase + kk * 32);
            ldsm4(b[1], bBase + 16 * ASTR + kk * 32);
            #pragma unroll
            for (int mt = 0; mt < 2; mt++)
                #pragma unroll
                for (int nt = 0; nt < 4; nt++)
                    mma16816(acc[mt][nt], a[mt], &b[nt >> 1][(nt & 1) * 2]);
        }

        // ---- epilogue at end of each state ----
        if (h == 1) {
            const float ld = logd_s[k];
            float be[4][2];
            #pragma unroll
            for (int nt = 0; nt < 4; nt++) {
                float2 v = *(const float2*)&beff_s[k * CDIM + wn * 32 + nt * 8 + tig * 2];
                be[nt][0] = v.x; be[nt][1] = v.y;
            }
            float ps[2][2];
            #pragma unroll
            for (int mt = 0; mt < 2; mt++)
                #pragma unroll
                for (int rh = 0; rh < 2; rh++) {
                    float sum = 0.f;
                    #pragma unroll
                    for (int nt = 0; nt < 4; nt++) {
                        const float z0 = acc[mt][nt][rh * 2 + 0] + be[nt][0];
                        const float z1 = acc[mt][nt][rh * 2 + 1] + be[nt][1];
                        sum = fmaf(z0, z0, sum);
                        sum = fmaf(z1, z1, sum);
                        acc[mt][nt][rh * 2 + 0] = 0.f;
                        acc[mt][nt][rh * 2 + 1] = 0.f;
                    }
                    sum += __shfl_xor_sync(0xffffffffu, sum, 1);
                    sum += __shfl_xor_sync(0xffffffffu, sum, 2);
                    ps[mt][rh] = sum;     // valid in all 4 tig lanes
                }
            // combine the two N-half warps via smem
            if (wn == 0 && tig == 0) {
                #pragma unroll
                for (int mt = 0; mt < 2; mt++)
                    #pragma unroll
                    for (int rh = 0; rh < 2; rh++)
                        red[wm * 32 + mt * 16 + rh * 8 + g] = ps[mt][rh];
            }
            __syncthreads();
            if (wn == 1 && tig == 0) {
                #pragma unroll
                for (int mt = 0; mt < 2; mt++)
                    #pragma unroll
                    for (int rh = 0; rh < 2; rh++) {
                        const int row = wm * 32 + mt * 16 + rh * 8 + g;
                        out[(size_t)k * TDIM + t0 + row] =
                            -0.5f * (117.62413225f + ld + red[row] + ps[mt][rh]);
                    }
            }
        }

        __syncthreads();                         // everyone done with buffer of s
        if (s + 2 < NHALF) {
            const int s2 = s + 2;
            loadB(sb + SMB, k0 + (s2 >> 1), s2 & 1, tid);   // reuses buffer of s
        }
        CP_COMMIT();
        if (s + 1 < NHALF) {
            CP_WAIT1();                          // half-step s+1 resident
            __syncthreads();
        }
    }
}

// ---------------- launch ----------------
extern "C" void kernel_launch(void* const* d_in, const int* in_sizes, int n_in,
                              void* d_out, int out_size) {
    const float* x     = (const float*)d_in[0];  // [1,64,65536]
    const float* W     = (const float*)d_in[1];  // [16,64,64,9]
    const float* b     = (const float*)d_in[2];  // [16,64]
    const float* Sigma = (const float*)d_in[3];  // [16,64,64]
    float* out = (float*)d_out;                  // [1,16,65536]
    (void)in_sizes; (void)n_in; (void)out_size;

    cudaFuncSetAttribute(main_kernel, cudaFuncAttributeMaxDynamicSharedMemorySize,
                         SMTOT);

    chol_kernel<<<KST, 32>>>(Sigma, b);
    dim3 wgrid(8, KST);
    weff_pack_kernel<<<wgrid, 256>>>(W);
    main_kernel<<<(TDIM / TM) * 2, 256, SMTOT>>>(x, out);
}

// round 6
// speedup vs baseline: 1.2872x; 1.2872x over previous
#include <cuda_runtime.h>
#include <cuda_fp16.h>
#include <math.h>
#include <stdint.h>

// ---------------- problem constants ----------------
#define KST   16
#define CDIM  64
#define TDIM  65536
#define KTOT  576            // 64*9 contraction length
#define TM    128            // time rows per tile (GEMM M)
#define ASTR  1168           // smem row stride bytes (584 halves)
#define SGRP  8              // states per block (2-way split)

// ---------------- device scratch ----------------
__device__ float  g_Lfac[KST * CDIM * CDIM];    // Cholesky factor L (lower, row-major)
__device__ float  g_logdet[KST];
__device__ float  g_beff[KST * CDIM];
__device__ __half g_WeffH[KST * CDIM * KTOT];   // [k][c][e], e = ci*9+j

// ---------------- helpers ----------------
__device__ __forceinline__ uint32_t s2u(const void* p) {
    uint32_t a;
    asm("{ .reg .u64 t; cvta.to.shared.u64 t, %1; cvt.u32.u64 %0, t; }" : "=r"(a) : "l"(p));
    return a;
}
__device__ __forceinline__ void ldsm4(uint32_t* r, uint32_t addr) {
    asm volatile("ldmatrix.sync.aligned.m8n8.x4.shared.b16 {%0,%1,%2,%3}, [%4];"
                 : "=r"(r[0]), "=r"(r[1]), "=r"(r[2]), "=r"(r[3]) : "r"(addr));
}
__device__ __forceinline__ void mma16816(float* d, const uint32_t* a, const uint32_t* b) {
    asm volatile(
        "mma.sync.aligned.m16n8k16.row.col.f32.f16.f16.f32 "
        "{%0,%1,%2,%3}, {%4,%5,%6,%7}, {%8,%9}, {%0,%1,%2,%3};"
        : "+f"(d[0]), "+f"(d[1]), "+f"(d[2]), "+f"(d[3])
        : "r"(a[0]), "r"(a[1]), "r"(a[2]), "r"(a[3]), "r"(b[0]), "r"(b[1]));
}
__device__ __forceinline__ void cpasync16(uint32_t dst, const void* src) {
    asm volatile("cp.async.cg.shared.global [%0], [%1], 16;" :: "r"(dst), "l"(src));
}
#define CP_COMMIT() asm volatile("cp.async.commit_group;" ::: "memory")
#define CP_WAIT1()  asm volatile("cp.async.wait_group 1;" ::: "memory")

// ================= 1) blocked Cholesky (panels of 8) + logdet =================
// grid 16 x 256. Warp 0 factors each 8-col panel (syncwarp only);
// all 256 threads do the rank-8 trailing update. ~16 block syncs total.
__global__ void chol_kernel(const float* __restrict__ Sigma) {
    const int k = blockIdx.x;
    const int tid = threadIdx.x;   // 256
    const int lane = tid & 31;
    __shared__ float S[CDIM * 65];
    __shared__ float lgs[CDIM];

    for (int idx = tid; idx < CDIM * CDIM; idx += 256)
        S[(idx >> 6) * 65 + (idx & 63)] = Sigma[k * CDIM * CDIM + idx];
    __syncthreads();

    for (int p = 0; p < 8; p++) {
        const int c0 = p * 8;
        // ---- panel factorization by warp 0 ----
        if (tid < 32) {
            for (int cc = 0; cc < 8; cc++) {
                const int col = c0 + cc;
                const float rinv = rsqrtf(S[col * 65 + col]);
                for (int r = col + lane; r < CDIM; r += 32)
                    S[r * 65 + col] *= rinv;
                __syncwarp();
                for (int r = col + 1 + lane; r < CDIM; r += 32) {
                    const float lr = S[r * 65 + col];
                    #pragma unroll
                    for (int c2 = col + 1; c2 < c0 + 8; c2++)
                        S[r * 65 + c2] -= lr * S[c2 * 65 + col];
                }
                __syncwarp();
            }
        }
        __syncthreads();
        // ---- rank-8 trailing update on remaining block ----
        const int rs = c0 + 8;
        const int nr = CDIM - rs;
        if (nr > 0) {
            for (int idx = tid; idx < nr * nr; idx += 256) {
                const int r = rs + idx / nr;
                const int c = rs + idx % nr;
                if (c <= r) {
                    float acc = 0.f;
                    #pragma unroll
                    for (int j = 0; j < 8; j++)
                        acc += S[r * 65 + c0 + j] * S[c * 65 + c0 + j];
                    S[r * 65 + c] -= acc;
                }
            }
            __syncthreads();
        }
    }

    if (tid < CDIM) lgs[tid] = logf(S[tid * 65 + tid]);
    __syncthreads();
    if (tid == 0) {
        float ld = 0.f;
        #pragma unroll
        for (int i = 0; i < CDIM; i++) ld += lgs[i];
        g_logdet[k] = 2.f * ld;
    }
    for (int idx = tid; idx < CDIM * CDIM; idx += 256) {
        const int r = idx >> 6, c = idx & 63;
        g_Lfac[k * CDIM * CDIM + idx] = (c <= r) ? S[r * 65 + c] : 0.f;
    }
}

// ========== 2) triangular solve L Y = [W | b], one RHS column per thread ==========
// grid (3, 16) x 256. Column e<576 -> Weff fp16; e==576 -> beff f32.
// Y register-resident, fully unrolled; L broadcast from smem; no inner syncs.
__global__ void solve_kernel(const float* __restrict__ W, const float* __restrict__ b) {
    const int k = blockIdx.y;
    const int tid = threadIdx.x;
    const int e = blockIdx.x * 256 + tid;
    __shared__ float L[CDIM * 65];
    __shared__ float dinv[CDIM];

    for (int idx = tid; idx < CDIM * CDIM; idx += 256)
        L[(idx >> 6) * 65 + (idx & 63)] = g_Lfac[k * CDIM * CDIM + idx];
    __syncthreads();
    if (tid < CDIM) dinv[tid] = 1.f / L[tid * 65 + tid];
    __syncthreads();

    if (e > KTOT) return;

    float Y[CDIM];
    if (e < KTOT) {
        const int ci = e / 9, jj = e - ci * 9;
        #pragma unroll
        for (int i = 0; i < CDIM; i++)
            Y[i] = W[((size_t)(k * CDIM + i) * CDIM + ci) * 9 + jj];
    } else {
        #pragma unroll
        for (int i = 0; i < CDIM; i++) Y[i] = b[k * CDIM + i];
    }

    #pragma unroll
    for (int i = 0; i < CDIM; i++) {
        float a0 = Y[i], a1 = 0.f, a2 = 0.f, a3 = 0.f;
        #pragma unroll
        for (int j = 0; j < i; j += 4) {
            a0 -= L[i * 65 + j] * Y[j];
            if (j + 1 < i) a1 -= L[i * 65 + j + 1] * Y[j + 1];
            if (j + 2 < i) a2 -= L[i * 65 + j + 2] * Y[j + 2];
            if (j + 3 < i) a3 -= L[i * 65 + j + 3] * Y[j + 3];
        }
        Y[i] = ((a0 + a1) + (a2 + a3)) * dinv[i];
    }

    if (e < KTOT) {
        #pragma unroll
        for (int i = 0; i < CDIM; i++)
            g_WeffH[((size_t)k * CDIM + i) * KTOT + e] = __float2half(Y[i]);
    } else {
        #pragma unroll
        for (int i = 0; i < CDIM; i++) g_beff[k * CDIM + i] = Y[i];
    }
}

// ================= 3) main: smem im2col A + mma.sync fp16, 8 warps =================
// grid 1024: tile = bx>>1 (512 t-tiles), state group sg = bx&1 (8 states each).
// smem bytes: A [0,149504), B [149504,224256), beff, logd, red
#define SMA   0
#define SMB   149504
#define SMBE  224256
#define SMLD  228352
#define SMRED 228416
#define SMTOT 228928

__device__ __forceinline__ void loadB(uint32_t sbB, int k, int h, int tid) {
    // half h: 288 halves per row starting at byte col h*576; 64 rows x 36 chunks
    #pragma unroll
    for (int i = 0; i < 9; i++) {
        const int lin = i * 256 + tid;          // 0..2303
        const int row = lin / 36, ch = lin - row * 36;
        const uint32_t dst = sbB + row * ASTR + h * 576 + ch * 16;
        const char* src = (const char*)g_WeffH +
                          ((size_t)k * CDIM + row) * (KTOT * 2) + h * 576 + ch * 16;
        cpasync16(dst, src);
    }
}

__global__ void __launch_bounds__(256, 1)
main_kernel(const float* __restrict__ x, float* __restrict__ out) {
    extern __shared__ __align__(1024) char smem[];
    const uint32_t sb = s2u(smem);
    const int tid = threadIdx.x;
    const int lane = tid & 31;
    const int w = tid >> 5;           // 8 warps
    const int wm = w & 3;             // M: rows [wm*32, +32)
    const int wn = w >> 2;            // N: cols [wn*32, +32)
    const int t0 = (blockIdx.x >> 1) * TM;
    const int k0 = (blockIdx.x & 1) * SGRP;

    float* beff_s = (float*)(smem + SMBE);
    float* logd_s = (float*)(smem + SMLD);
    float* red    = (float*)(smem + SMRED);

    // prefetch B for half-steps 0 and 1 (state k0)
    loadB(sb + SMB, k0, 0, tid); CP_COMMIT();
    loadB(sb + SMB, k0, 1, tid); CP_COMMIT();

    // ---- build A (im2col fp16): 2 threads per row, 16 channel-pairs each ----
    {
        const int row = tid >> 1, half = tid & 1;
        __half* Arow = (__half*)(smem + SMA + row * ASTR);
        const int tb = t0 + row - 8;
        #pragma unroll 4
        for (int pp = 0; pp < 16; pp++) {
            const int p = half * 16 + pp;        // channel pair (2p, 2p+1)
            float v[18];
            const float* x0 = x + (size_t)(2 * p) * TDIM;
            const float* x1 = x0 + TDIM;
            #pragma unroll
            for (int j = 0; j < 9; j++) {
                const int gt = tb + j;
                v[j]     = (gt >= 0) ? __ldg(x0 + gt) : 0.f;
                v[9 + j] = (gt >= 0) ? __ldg(x1 + gt) : 0.f;
            }
            uint32_t* dst = (uint32_t*)(Arow + p * 18);   // 36B-aligned
            #pragma unroll
            for (int qq = 0; qq < 9; qq++) {
                __half2 hh = __floats2half2_rn(v[2 * qq], v[2 * qq + 1]);
                dst[qq] = *(uint32_t*)&hh;
            }
        }
    }
    for (int idx = tid; idx < KST * CDIM; idx += 256) beff_s[idx] = g_beff[idx];
    if (tid < KST) logd_s[tid] = g_logdet[tid];

    // ldmatrix per-thread base addresses
    const int mat = lane >> 3, lr = lane & 7;
    const uint32_t aBase = sb + SMA + (wm * 32 + (mat & 1) * 8 + lr) * ASTR + (mat >> 1) * 16;
    const uint32_t bBase = sb + SMB + (wn * 32 + (mat >> 1) * 8 + lr) * ASTR + (mat & 1) * 16;
    const int g = lane >> 2, tig = lane & 3;

    float acc[2][4][4];
    #pragma unroll
    for (int mt = 0; mt < 2; mt++)
        #pragma unroll
        for (int nt = 0; nt < 4; nt++)
            #pragma unroll
            for (int i = 0; i < 4; i++) acc[mt][nt][i] = 0.f;

    CP_WAIT1();              // half-step 0 resident
    __syncthreads();         // A + B(k0,0) visible everywhere

    const int NHALF = 2 * SGRP;
    for (int s = 0; s < NHALF; s++) {
        const int k = k0 + (s >> 1), h = s & 1;

        // ---- compute half-step s : k-steps [h*18, h*18+18) ----
        #pragma unroll 3
        for (int kk = h * 18; kk < h * 18 + 18; kk++) {
            uint32_t a[2][4], b[2][4];
            ldsm4(a[0], aBase + kk * 32);
            ldsm4(a[1], aBase + 16 * ASTR + kk * 32);
            ldsm4(b[0], bBase + kk * 32);
            ldsm4(b[1], bBase + 16 * ASTR + kk * 32);
            #pragma unroll
            for (int mt = 0; mt < 2; mt++)
                #pragma unroll
                for (int nt = 0; nt < 4; nt++)
                    mma16816(acc[mt][nt], a[mt], &b[nt >> 1][(nt & 1) * 2]);
        }

        // ---- epilogue at end of each state ----
        if (h == 1) {
            const float ld = logd_s[k];
            float be[4][2];
            #pragma unroll
            for (int nt = 0; nt < 4; nt++) {
                float2 v = *(const float2*)&beff_s[k * CDIM + wn * 32 + nt * 8 + tig * 2];
                be[nt][0] = v.x; be[nt][1] = v.y;
            }
            float ps[2][2];
            #pragma unroll
            for (int mt = 0; mt < 2; mt++)
                #pragma unroll
                for (int rh = 0; rh < 2; rh++) {
                    float sum = 0.f;
                    #pragma unroll
                    for (int nt = 0; nt < 4; nt++) {
                        const float z0 = acc[mt][nt][rh * 2 + 0] + be[nt][0];
                        const float z1 = acc[mt][nt][rh * 2 + 1] + be[nt][1];
                        sum = fmaf(z0, z0, sum);
                        sum = fmaf(z1, z1, sum);
                        acc[mt][nt][rh * 2 + 0] = 0.f;
                        acc[mt][nt][rh * 2 + 1] = 0.f;
                    }
                    sum += __shfl_xor_sync(0xffffffffu, sum, 1);
                    sum += __shfl_xor_sync(0xffffffffu, sum, 2);
                    ps[mt][rh] = sum;     // valid in all 4 tig lanes
                }
            // combine the two N-half warps via smem
            if (wn == 0 && tig == 0) {
                #pragma unroll
                for (int mt = 0; mt < 2; mt++)
                    #pragma unroll
                    for (int rh = 0; rh < 2; rh++)
                        red[wm * 32 + mt * 16 + rh * 8 + g] = ps[mt][rh];
            }
            __syncthreads();
            if (wn == 1 && tig == 0) {
                #pragma unroll
                for (int mt = 0; mt < 2; mt++)
                    #pragma unroll
                    for (int rh = 0; rh < 2; rh++) {
                        const int row = wm * 32 + mt * 16 + rh * 8 + g;
                        out[(size_t)k * TDIM + t0 + row] =
                            -0.5f * (117.62413225f + ld + red[row] + ps[mt][rh]);
                    }
            }
        }

        __syncthreads();                         // everyone done with buffer of s
        if (s + 2 < NHALF) {
            const int s2 = s + 2;
            loadB(sb + SMB, k0 + (s2 >> 1), s2 & 1, tid);   // reuses buffer of s
        }
        CP_COMMIT();
        if (s + 1 < NHALF) {
            CP_WAIT1();                          // half-step s+1 resident
            __syncthreads();
        }
    }
}

// ---------------- launch ----------------
extern "C" void kernel_launch(void* const* d_in, const int* in_sizes, int n_in,
                              void* d_out, int out_size) {
    const float* x     = (const float*)d_in[0];  // [1,64,65536]
    const float* W     = (const float*)d_in[1];  // [16,64,64,9]
    const float* b     = (const float*)d_in[2];  // [16,64]
    const float* Sigma = (const float*)d_in[3];  // [16,64,64]
    float* out = (float*)d_out;                  // [1,16,65536]
    (void)in_sizes; (void)n_in; (void)out_size;

    cudaFuncSetAttribute(main_kernel, cudaFuncAttributeMaxDynamicSharedMemorySize,
                         SMTOT);

    chol_kernel<<<KST, 256>>>(Sigma);
    dim3 sgrid(3, KST);
    solve_kernel<<<sgrid, 256>>>(W, b);
    main_kernel<<<(TDIM / TM) * 2, 256, SMTOT>>>(x, out);
}

// round 7
// speedup vs baseline: 1.3421x; 1.0426x over previous
#include <cuda_runtime.h>
#include <cuda_fp16.h>
#include <math.h>
#include <stdint.h>

// ---------------- problem constants ----------------
#define KST   16
#define CDIM  64
#define TDIM  65536
#define KTOT  576            // 64*9 contraction length
#define TM    128            // time rows per tile (GEMM M)
#define ASTR  1168           // smem row stride bytes (584 halves)
#define SGRP  8              // states per block (2-way split)

// ---------------- device scratch ----------------
__device__ float  g_logdet[KST];
__device__ float  g_beff[KST * CDIM];
__device__ __half g_WeffH[KST * CDIM * KTOT];   // [k][c][e], e = ci*9+j

// ---------------- helpers ----------------
__device__ __forceinline__ uint32_t s2u(const void* p) {
    uint32_t a;
    asm("{ .reg .u64 t; cvta.to.shared.u64 t, %1; cvt.u32.u64 %0, t; }" : "=r"(a) : "l"(p));
    return a;
}
__device__ __forceinline__ void ldsm4(uint32_t* r, uint32_t addr) {
    asm volatile("ldmatrix.sync.aligned.m8n8.x4.shared.b16 {%0,%1,%2,%3}, [%4];"
                 : "=r"(r[0]), "=r"(r[1]), "=r"(r[2]), "=r"(r[3]) : "r"(addr));
}
__device__ __forceinline__ void mma16816(float* d, const uint32_t* a, const uint32_t* b) {
    asm volatile(
        "mma.sync.aligned.m16n8k16.row.col.f32.f16.f16.f32 "
        "{%0,%1,%2,%3}, {%4,%5,%6,%7}, {%8,%9}, {%0,%1,%2,%3};"
        : "+f"(d[0]), "+f"(d[1]), "+f"(d[2]), "+f"(d[3])
        : "r"(a[0]), "r"(a[1]), "r"(a[2]), "r"(a[3]), "r"(b[0]), "r"(b[1]));
}
__device__ __forceinline__ void cpasync16(uint32_t dst, const void* src) {
    asm volatile("cp.async.cg.shared.global [%0], [%1], 16;" :: "r"(dst), "l"(src));
}
#define CP_COMMIT() asm volatile("cp.async.commit_group;" ::: "memory")
#define CP_WAIT1()  asm volatile("cp.async.wait_group 1;" ::: "memory")

// ====== 1) fused precompute: left-looking Cholesky + triangular solve ======
// grid (4, 16) x 256. Each block redundantly factors Sigma_k in smem
// (left-looking, row-per-thread, 2 barriers/column), then solves its quarter
// of the 577 RHS columns (L Y = [W | b]) with register-resident Y.
__global__ void prep_kernel(const float* __restrict__ Sigma,
                            const float* __restrict__ W,
                            const float* __restrict__ b) {
    const int q = blockIdx.x;       // column quarter
    const int k = blockIdx.y;       // state
    const int tid = threadIdx.x;    // 256
    __shared__ float L[CDIM * 65];
    __shared__ float sdiag[CDIM];
    __shared__ float dinv[CDIM];
    __shared__ float lgs[CDIM];

    for (int idx = tid; idx < CDIM * CDIM; idx += 256)
        L[(idx >> 6) * 65 + (idx & 63)] = Sigma[k * CDIM * CDIM + idx];
    __syncthreads();

    // ---- left-looking Cholesky: thread r owns row r (tid < 64 active) ----
    const int r = tid;
    for (int j = 0; j < CDIM; j++) {
        float acc = 0.f;
        if (r < CDIM && r >= j) {
            float a0 = 0.f, a1 = 0.f, a2 = 0.f, a3 = 0.f;
            int kk = 0;
            for (; kk + 4 <= j; kk += 4) {
                a0 += L[r * 65 + kk]     * L[j * 65 + kk];
                a1 += L[r * 65 + kk + 1] * L[j * 65 + kk + 1];
                a2 += L[r * 65 + kk + 2] * L[j * 65 + kk + 2];
                a3 += L[r * 65 + kk + 3] * L[j * 65 + kk + 3];
            }
            for (; kk < j; kk++) a0 += L[r * 65 + kk] * L[j * 65 + kk];
            acc = L[r * 65 + j] - (((a0 + a1) + (a2 + a3)));
            if (r == j) { sdiag[j] = acc; lgs[j] = logf(acc); }
        }
        __syncthreads();
        if (r < CDIM && r >= j) {
            const float rinv = rsqrtf(sdiag[j]);
            L[r * 65 + j] = acc * rinv;     // r==j stores sqrt(d) (unused later)
        }
        __syncthreads();
    }

    // logdet(Sigma) = sum_j log(d_j)   (d_j = L_jj^2 pre-scaling)
    if (q == 0 && tid < 32) {
        float v = lgs[tid] + lgs[tid + 32];
        #pragma unroll
        for (int o = 16; o; o >>= 1) v += __shfl_xor_sync(0xffffffffu, v, o);
        if (tid == 0) g_logdet[k] = v;
    }
    if (tid < CDIM) dinv[tid] = rsqrtf(sdiag[tid]);   // 1 / L_ii
    __syncthreads();

    // ---- triangular solve: column e = 4*tid + q of [W | b] ----
    const int e = 4 * tid + q;
    if (e > KTOT) return;

    float Y[CDIM];
    if (e < KTOT) {
        const int ci = e / 9, jj = e - ci * 9;
        #pragma unroll
        for (int i = 0; i < CDIM; i++)
            Y[i] = W[((size_t)(k * CDIM + i) * CDIM + ci) * 9 + jj];
    } else {
        #pragma unroll
        for (int i = 0; i < CDIM; i++) Y[i] = b[k * CDIM + i];
    }

    #pragma unroll
    for (int i = 0; i < CDIM; i++) {
        float a0 = Y[i], a1 = 0.f, a2 = 0.f, a3 = 0.f;
        #pragma unroll
        for (int j = 0; j < i; j += 4) {
            a0 -= L[i * 65 + j] * Y[j];
            if (j + 1 < i) a1 -= L[i * 65 + j + 1] * Y[j + 1];
            if (j + 2 < i) a2 -= L[i * 65 + j + 2] * Y[j + 2];
            if (j + 3 < i) a3 -= L[i * 65 + j + 3] * Y[j + 3];
        }
        Y[i] = (((a0 + a1) + (a2 + a3))) * dinv[i];
    }

    if (e < KTOT) {
        #pragma unroll
        for (int i = 0; i < CDIM; i++)
            g_WeffH[((size_t)k * CDIM + i) * KTOT + e] = __float2half(Y[i]);
    } else {
        #pragma unroll
        for (int i = 0; i < CDIM; i++) g_beff[k * CDIM + i] = Y[i];
    }
}

// ================= 2) main: smem im2col A + mma.sync fp16, 8 warps =================
// grid 1024: tile = bx>>1 (512 t-tiles), state group sg = bx&1 (8 states each).
// smem bytes: A [0,149504), B [149504,224256), beff, logd, red
#define SMA   0
#define SMB   149504
#define SMBE  224256
#define SMLD  228352
#define SMRED 228416
#define SMTOT 228928

__device__ __forceinline__ void loadB(uint32_t sbB, int k, int h, int tid) {
    // half h: 288 halves per row starting at byte col h*576; 64 rows x 36 chunks
    #pragma unroll
    for (int i = 0; i < 9; i++) {
        const int lin = i * 256 + tid;          // 0..2303
        const int row = lin / 36, ch = lin - row * 36;
        const uint32_t dst = sbB + row * ASTR + h * 576 + ch * 16;
        const char* src = (const char*)g_WeffH +
                          ((size_t)k * CDIM + row) * (KTOT * 2) + h * 576 + ch * 16;
        cpasync16(dst, src);
    }
}

__global__ void __launch_bounds__(256, 1)
main_kernel(const float* __restrict__ x, float* __restrict__ out) {
    extern __shared__ __align__(1024) char smem[];
    const uint32_t sb = s2u(smem);
    const int tid = threadIdx.x;
    const int lane = tid & 31;
    const int w = tid >> 5;           // 8 warps
    const int wm = w & 3;             // M: rows [wm*32, +32)
    const int wn = w >> 2;            // N: cols [wn*32, +32)
    const int t0 = (blockIdx.x >> 1) * TM;
    const int k0 = (blockIdx.x & 1) * SGRP;

    float* beff_s = (float*)(smem + SMBE);
    float* logd_s = (float*)(smem + SMLD);
    float* red    = (float*)(smem + SMRED);

    // prefetch B for half-steps 0 and 1 (state k0)
    loadB(sb + SMB, k0, 0, tid); CP_COMMIT();
    loadB(sb + SMB, k0, 1, tid); CP_COMMIT();

    // ---- build A (im2col fp16): 2 threads per row, 16 channel-pairs each ----
    {
        const int row = tid >> 1, half = tid & 1;
        __half* Arow = (__half*)(smem + SMA + row * ASTR);
        const int tb = t0 + row - 8;
        #pragma unroll 4
        for (int pp = 0; pp < 16; pp++) {
            const int p = half * 16 + pp;        // channel pair (2p, 2p+1)
            float v[18];
            const float* x0 = x + (size_t)(2 * p) * TDIM;
            const float* x1 = x0 + TDIM;
            #pragma unroll
            for (int j = 0; j < 9; j++) {
                const int gt = tb + j;
                v[j]     = (gt >= 0) ? __ldg(x0 + gt) : 0.f;
                v[9 + j] = (gt >= 0) ? __ldg(x1 + gt) : 0.f;
            }
            uint32_t* dst = (uint32_t*)(Arow + p * 18);   // 36B-aligned
            #pragma unroll
            for (int qq = 0; qq < 9; qq++) {
                __half2 hh = __floats2half2_rn(v[2 * qq], v[2 * qq + 1]);
                dst[qq] = *(uint32_t*)&hh;
            }
        }
    }
    for (int idx = tid; idx < KST * CDIM; idx += 256) beff_s[idx] = g_beff[idx];
    if (tid < KST) logd_s[tid] = g_logdet[tid];

    // ldmatrix per-thread base addresses
    const int mat = lane >> 3, lr = lane & 7;
    const uint32_t aBase = sb + SMA + (wm * 32 + (mat & 1) * 8 + lr) * ASTR + (mat >> 1) * 16;
    const uint32_t bBase = sb + SMB + (wn * 32 + (mat >> 1) * 8 + lr) * ASTR + (mat & 1) * 16;
    const int g = lane >> 2, tig = lane & 3;

    float acc[2][4][4];
    #pragma unroll
    for (int mt = 0; mt < 2; mt++)
        #pragma unroll
        for (int nt = 0; nt < 4; nt++)
            #pragma unroll
            for (int i = 0; i < 4; i++) acc[mt][nt][i] = 0.f;

    CP_WAIT1();              // half-step 0 resident
    __syncthreads();         // A + B(k0,0) visible everywhere

    const int NHALF = 2 * SGRP;
    for (int s = 0; s < NHALF; s++) {
        const int k = k0 + (s >> 1), h = s & 1;

        // ---- compute half-step s : k-steps [h*18, h*18+18) ----
        #pragma unroll 3
        for (int kk = h * 18; kk < h * 18 + 18; kk++) {
            uint32_t a[2][4], b[2][4];
            ldsm4(a[0], aBase + kk * 32);
            ldsm4(a[1], aBase + 16 * ASTR + kk * 32);
            ldsm4(b[0], bBase + kk * 32);
            ldsm4(b[1], bBase + 16 * ASTR + kk * 32);
            #pragma unroll
            for (int mt = 0; mt < 2; mt++)
                #pragma unroll
                for (int nt = 0; nt < 4; nt++)
                    mma16816(acc[mt][nt], a[mt], &b[nt >> 1][(nt & 1) * 2]);
        }

        // ---- epilogue at end of each state ----
        if (h == 1) {
            const float ld = logd_s[k];
            float be[4][2];
            #pragma unroll
            for (int nt = 0; nt < 4; nt++) {
                float2 v = *(const float2*)&beff_s[k * CDIM + wn * 32 + nt * 8 + tig * 2];
                be[nt][0] = v.x; be[nt][1] = v.y;
            }
            float ps[2][2];
            #pragma unroll
            for (int mt = 0; mt < 2; mt++)
                #pragma unroll
                for (int rh = 0; rh < 2; rh++) {
                    float sum = 0.f;
                    #pragma unroll
                    for (int nt = 0; nt < 4; nt++) {
                        const float z0 = acc[mt][nt][rh * 2 + 0] + be[nt][0];
                        const float z1 = acc[mt][nt][rh * 2 + 1] + be[nt][1];
                        sum = fmaf(z0, z0, sum);
                        sum = fmaf(z1, z1, sum);
                        acc[mt][nt][rh * 2 + 0] = 0.f;
                        acc[mt][nt][rh * 2 + 1] = 0.f;
                    }
                    sum += __shfl_xor_sync(0xffffffffu, sum, 1);
                    sum += __shfl_xor_sync(0xffffffffu, sum, 2);
                    ps[mt][rh] = sum;     // valid in all 4 tig lanes
                }
            // combine the two N-half warps via smem
            if (wn == 0 && tig == 0) {
                #pragma unroll
                for (int mt = 0; mt < 2; mt++)
                    #pragma unroll
                    for (int rh = 0; rh < 2; rh++)
                        red[wm * 32 + mt * 16 + rh * 8 + g] = ps[mt][rh];
            }
            __syncthreads();
            if (wn == 1 && tig == 0) {
                #pragma unroll
                for (int mt = 0; mt < 2; mt++)
                    #pragma unroll
                    for (int rh = 0; rh < 2; rh++) {
                        const int row = wm * 32 + mt * 16 + rh * 8 + g;
                        out[(size_t)k * TDIM + t0 + row] =
                            -0.5f * (117.62413225f + ld + red[row] + ps[mt][rh]);
                    }
            }
        }

        __syncthreads();                         // everyone done with buffer of s
        if (s + 2 < NHALF) {
            const int s2 = s + 2;
            loadB(sb + SMB, k0 + (s2 >> 1), s2 & 1, tid);   // reuses buffer of s
        }
        CP_COMMIT();
        if (s + 1 < NHALF) {
            CP_WAIT1();                          // half-step s+1 resident
            __syncthreads();
        }
    }
}

// ---------------- launch ----------------
extern "C" void kernel_launch(void* const* d_in, const int* in_sizes, int n_in,
                              void* d_out, int out_size) {
    const float* x     = (const float*)d_in[0];  // [1,64,65536]
    const float* W     = (const float*)d_in[1];  // [16,64,64,9]
    const float* b     = (const float*)d_in[2];  // [16,64]
    const float* Sigma = (const float*)d_in[3];  // [16,64,64]
    float* out = (float*)d_out;                  // [1,16,65536]
    (void)in_sizes; (void)n_in; (void)out_size;

    cudaFuncSetAttribute(main_kernel, cudaFuncAttributeMaxDynamicSharedMemorySize,
                         SMTOT);

    dim3 pgrid(4, KST);
    prep_kernel<<<pgrid, 256>>>(Sigma, W, b);
    main_kernel<<<(TDIM / TM) * 2, 256, SMTOT>>>(x, out);
}